// round 12
// baseline (speedup 1.0000x reference)
#include <cuda_runtime.h>
#include <cstdint>

#define NPTS 8192
#define DIM  256           // elements per row (256 int8 bytes)
#define KNN  11
#define TM   128
#define TN   128
#define HALF 4096
#define NCT  32            // col tiles per CTA
#define NTHREADS 512
#define PAB  272           // smem pitch in BYTES (256 + 16)
#define BIGF 1e30f

// smem byte offsets
#define SMB_A    0
#define TILE_B   (128 * PAB)            // 34816 bytes per tile buffer
#define SMB_B    TILE_B                 // two B buffers follow A
#define SMB_RS   (TILE_B * 3)           // 104448
#define SMB_HEAP (SMB_RS + 2048)        // 106496
#define SM_TOTAL (SMB_HEAP + NTHREADS * 45 * 4)   // + 92160 = 198656 B

__device__ __align__(16) char g_xq[(size_t)NPTS * DIM];
__device__ float g_sq[NPTS];
__device__ float g_inv[NPTS];
__device__ __align__(16) float g_meta[2 * NPTS];   // (sq, inv) per column
__device__ float g_colpart[128 * DIM];
__device__ float g_psum[2 * NPTS];
__device__ float g_ptopk[(size_t)2 * NPTS * 12];
__device__ float g_disc[64];

__device__ __forceinline__ uint32_t smem_u32(const void* p) {
    uint32_t a;
    asm("{ .reg .u64 t; cvta.to.shared.u64 t, %1; cvt.u32.u64 %0, t; }"
        : "=r"(a) : "l"(p));
    return a;
}
__device__ __forceinline__ void cpasync16(uint32_t dst, const void* src) {
    asm volatile("cp.async.cg.shared.global [%0], [%1], 16;"
                 :: "r"(dst), "l"(src) : "memory");
}
#define CP_COMMIT() asm volatile("cp.async.commit_group;" ::: "memory")
#define CP_WAIT0()  asm volatile("cp.async.wait_group 0;" ::: "memory")

__device__ __forceinline__ void ldsm4(uint32_t& r0, uint32_t& r1,
                                      uint32_t& r2, uint32_t& r3, uint32_t a) {
    asm volatile("ldmatrix.sync.aligned.m8n8.x4.shared.b16 {%0,%1,%2,%3}, [%4];"
                 : "=r"(r0), "=r"(r1), "=r"(r2), "=r"(r3) : "r"(a));
}
__device__ __forceinline__ void mma_s8(int* d, const uint32_t* a,
                                       const uint32_t* b) {
    asm volatile(
        "mma.sync.aligned.m16n8k32.row.col.s32.s8.s8.s32 "
        "{%0,%1,%2,%3}, {%4,%5,%6,%7}, {%8,%9}, {%0,%1,%2,%3};"
        : "+r"(d[0]), "+r"(d[1]), "+r"(d[2]), "+r"(d[3])
        : "r"(a[0]), "r"(a[1]), "r"(a[2]), "r"(a[3]), "r"(b[0]), "r"(b[1]));
}

// replace-max insert into unsorted 11-slot smem heap; th = new max
__device__ __forceinline__ void hins(float* hp, float& th, float d) {
    float mx1 = -BIGF, mx2 = -BIGF;
    int im = 0;
    #pragma unroll
    for (int t = 0; t < KNN; t++) {
        float v = hp[t];
        if (v > mx1) { mx2 = mx1; mx1 = v; im = t; }
        else mx2 = fmaxf(mx2, v);
    }
    hp[im] = d;
    th = fmaxf(mx2, d);
}

// sorted-array insert (merge kernels): hh ascending, caller checked d < hh[10]
__device__ __forceinline__ void ins11(float* hh, float d) {
    hh[10] = d;
    #pragma unroll
    for (int t = 10; t > 0; t--) {
        float lo = fminf(hh[t - 1], hh[t]);
        float hi = fmaxf(hh[t - 1], hh[t]);
        hh[t - 1] = lo; hh[t] = hi;
    }
}

// ---- quantize rows to int8 + exact fp32 norms + per-row scale ----
__global__ void tg_quant_kernel(const float* __restrict__ x) {
    int row  = (blockIdx.x * blockDim.x + threadIdx.x) >> 5;
    int lane = threadIdx.x & 31;
    const float* r = x + (size_t)row * DIM + lane * 8;
    float4 v0 = *(const float4*)(r);
    float4 v1 = *(const float4*)(r + 4);
    float sq = v0.x * v0.x + v0.y * v0.y + v0.z * v0.z + v0.w * v0.w +
               v1.x * v1.x + v1.y * v1.y + v1.z * v1.z + v1.w * v1.w;
    float am = fmaxf(fmaxf(fmaxf(fabsf(v0.x), fabsf(v0.y)),
                           fmaxf(fabsf(v0.z), fabsf(v0.w))),
                     fmaxf(fmaxf(fabsf(v1.x), fabsf(v1.y)),
                           fmaxf(fabsf(v1.z), fabsf(v1.w))));
    #pragma unroll
    for (int o = 16; o; o >>= 1) {
        sq += __shfl_xor_sync(0xffffffffu, sq, o);
        am = fmaxf(am, __shfl_xor_sync(0xffffffffu, am, o));
    }
    float s = 127.f / am;
    int q[8];
    q[0] = __float2int_rn(v0.x * s); q[1] = __float2int_rn(v0.y * s);
    q[2] = __float2int_rn(v0.z * s); q[3] = __float2int_rn(v0.w * s);
    q[4] = __float2int_rn(v1.x * s); q[5] = __float2int_rn(v1.y * s);
    q[6] = __float2int_rn(v1.z * s); q[7] = __float2int_rn(v1.w * s);
    uint32_t p0 = (q[0] & 255) | ((q[1] & 255) << 8) |
                  ((q[2] & 255) << 16) | ((uint32_t)(q[3] & 255) << 24);
    uint32_t p1 = (q[4] & 255) | ((q[5] & 255) << 8) |
                  ((q[6] & 255) << 16) | ((uint32_t)(q[7] & 255) << 24);
    ((uint2*)(g_xq + (size_t)row * DIM))[lane] = make_uint2(p0, p1);
    if (lane == 0) {
        float inv = am * (1.f / 127.f);
        g_sq[row]  = sq;
        g_inv[row] = inv;
        g_meta[2 * row]     = sq;
        g_meta[2 * row + 1] = inv;
    }
}

// ---- GDDM column sums ----
__global__ void tg_coldiff_kernel(const float* __restrict__ src,
                                  const float* __restrict__ tgt) {
    int d = threadIdx.x;
    int b = blockIdx.x;
    int r0 = b * (NPTS / 128);
    float s = 0.f;
    for (int r = 0; r < NPTS / 128; r++) {
        size_t idx = (size_t)(r0 + r) * DIM + d;
        s += src[idx] - tgt[idx];
    }
    g_colpart[b * DIM + d] = s;
}

// one k-step of IMMAs for the current tile
#define MMA_KSTEP(accN, bofs, kk) do {                                        \
    const uint32_t kby_ = (kk) * 32;                                          \
    uint32_t af0_[4], af1_[4], bf0_[4], bf1_[4];                              \
    ldsm4(af0_[0], af0_[1], af0_[2], af0_[3], aaddr[0] + kby_);               \
    ldsm4(af1_[0], af1_[1], af1_[2], af1_[3], aaddr[1] + kby_);               \
    ldsm4(bf0_[0], bf0_[1], bf0_[2], bf0_[3], baddr0[0] + (bofs) + kby_);     \
    ldsm4(bf1_[0], bf1_[1], bf1_[2], bf1_[3], baddr0[1] + (bofs) + kby_);     \
    mma_s8((accN) +  0, af0_, &bf0_[0]);  mma_s8((accN) +  4, af0_, &bf0_[2]);\
    mma_s8((accN) +  8, af0_, &bf1_[0]);  mma_s8((accN) + 12, af0_, &bf1_[2]);\
    mma_s8((accN) + 16, af1_, &bf0_[0]);  mma_s8((accN) + 20, af1_, &bf0_[2]);\
    mma_s8((accN) + 24, af1_, &bf1_[0]);  mma_s8((accN) + 28, af1_, &bf1_[2]);\
} while (0)

// epilogue for pair p (2 distance elements) of the previous tile's acc
#define EPI_PAIR(accE, p) do {                                                \
    const int ni_ = (p) >> 2, mi_ = ((p) >> 1) & 1, hf_ = (p) & 1;            \
    const int s_  = mi_ * 2 + hf_;                                            \
    float f0_ = __int2float_rn((accE)[mi_ * 16 + ni_ * 4 + hf_ * 2 + 0]);     \
    float f1_ = __int2float_rn((accE)[mi_ * 16 + ni_ * 4 + hf_ * 2 + 1]);     \
    float d2a_ = fmaf(f0_, mt[ni_].y * pinv[s_], sa[s_] + mt[ni_].x);         \
    float d2b_ = fmaf(f1_, mt[ni_].w * pinv[s_], sa[s_] + mt[ni_].z);         \
    d2a_ = fmaxf(d2a_, 1e-12f);  d2b_ = fmaxf(d2b_, 1e-12f);                  \
    float da_ = d2a_ * rsqrtf(d2a_);                                          \
    float db_ = d2b_ * rsqrtf(d2b_);                                          \
    rowsum[s_] += da_ + db_;                                                  \
    if (da_ < th[s_]) hins(hp + s_ * KNN, th[s_], da_);                       \
    if (db_ < th[s_]) hins(hp + s_ * KNN, th[s_], db_);                       \
} while (0)

// ---- main: int8 IMMA Gram, epilogue pipelined into next tile's MMAs ----
__global__ void __launch_bounds__(NTHREADS)
tg_main_kernel()
{
    extern __shared__ char sm[];
    const uint32_t smb = smem_u32(sm);
    float* rsbuf = (float*)(sm + SMB_RS);
    float* heap  = (float*)(sm + SMB_HEAP);

    const int tid  = threadIdx.x;
    const int lane = tid & 31;
    const int warp = tid >> 5;
    const int wr   = warp >> 2;          // 0..3: 32-row group
    const int wc   = warp & 3;           // 0..3: 32-col group
    const int qid  = lane >> 2;          // 0..7
    const int qt   = lane & 3;           // 0..3
    const int rt   = blockIdx.x >> 1;
    const int h    = blockIdx.x & 1;
    const int rowbase = rt * TM;
    const int colhalf = h * HALF;

    // ldmatrix per-lane addresses
    const int lr8 = lane & 7;
    const int a_m  = ((lane >> 3) & 1) * 8 + lr8;
    const int a_kb = (lane >> 4) * 16;
    uint32_t aaddr[2];
    #pragma unroll
    for (int mi = 0; mi < 2; mi++)
        aaddr[mi] = smb + SMB_A +
                    (uint32_t)((wr * 32 + mi * 16 + a_m) * PAB) + a_kb;
    const int b_n  = ((lane >> 4) & 1) * 8 + lr8;
    const int b_kb = ((lane >> 3) & 1) * 16;
    uint32_t baddr0[2];
    #pragma unroll
    for (int g = 0; g < 2; g++)
        baddr0[g] = smb + SMB_B +
                    (uint32_t)((wc * 32 + g * 16 + b_n) * PAB) + b_kb;

    // init per-thread smem heap (4 sets x 11, stride 45 floats)
    float* hp = heap + tid * 45;
    #pragma unroll
    for (int t = 0; t < 4 * KNN; t++) hp[t] = BIGF;
    float th[4] = {BIGF, BIGF, BIGF, BIGF};

    // stage A tile + B tiles 0 and 1
    {
        const char* Ag  = g_xq + (size_t)rowbase * DIM;
        const char* Bg0 = g_xq + (size_t)colhalf * DIM;
        const char* Bg1 = g_xq + (size_t)(colhalf + TN) * DIM;
        #pragma unroll
        for (int p = 0; p < 4; p++) {
            int idx = tid + p * NTHREADS;    // 0..2047
            int r = idx >> 4, f = idx & 15;
            cpasync16(smb + SMB_A + r * PAB + f * 16, Ag + r * DIM + f * 16);
            cpasync16(smb + SMB_B + r * PAB + f * 16, Bg0 + r * DIM + f * 16);
            cpasync16(smb + SMB_B + TILE_B + r * PAB + f * 16,
                      Bg1 + r * DIM + f * 16);
        }
        CP_COMMIT();
    }

    float sa[4], pinv[4];
    #pragma unroll
    for (int s = 0; s < 4; s++) {
        int row = rowbase + wr * 32 + s * 8 + qid;
        sa[s]   = g_sq[row];
        pinv[s] = -2.f * g_inv[row];
    }
    float rowsum[4] = {0.f, 0.f, 0.f, 0.f};

    int accA[32], accB[32];

    CP_WAIT0();
    __syncthreads();

    // prologue: tile 0 MMAs into accA
    #pragma unroll
    for (int j = 0; j < 32; j++) accA[j] = 0;
    #pragma unroll
    for (int kk = 0; kk < 8; kk++) MMA_KSTEP(accA, 0u, kk);
    __syncthreads();     // all warps done reading buf0 before iter0 prefetch

    for (int ct = 0; ct < NCT; ct++) {
        // prefetch tile ct+2 into buf ct&1 (tile ct's reads finished last iter)
        if (ct + 2 < NCT) {
            const char* Bg = g_xq + (size_t)(colhalf + (ct + 2) * TN) * DIM;
            uint32_t dst = smb + SMB_B + (ct & 1) * TILE_B;
            #pragma unroll
            for (int p = 0; p < 4; p++) {
                int idx = tid + p * NTHREADS;
                int r = idx >> 4, f = idx & 15;
                cpasync16(dst + r * PAB + f * 16, Bg + r * DIM + f * 16);
            }
            CP_COMMIT();
        }

        int* accEp = (ct & 1) ? accB : accA;
        int* accNx = (ct & 1) ? accA : accB;

        // column meta for the epilogue tile (ct)
        const int colEp = colhalf + ct * TN;
        float4 mt[4];
        #pragma unroll
        for (int ni = 0; ni < 4; ni++)
            mt[ni] = __ldg((const float4*)
                (g_meta + 2 * (colEp + wc * 32 + ni * 8 + 2 * qt)));

        if (ct + 1 < NCT) {
            const uint32_t bofs = ((ct + 1) & 1) * TILE_B;
            #pragma unroll
            for (int j = 0; j < 32; j++) accNx[j] = 0;
            #pragma unroll
            for (int kk = 0; kk < 8; kk++) {
                MMA_KSTEP(accNx, bofs, kk);
                EPI_PAIR(accEp, 2 * kk + 0);
                EPI_PAIR(accEp, 2 * kk + 1);
            }
        } else {
            #pragma unroll
            for (int p = 0; p < 16; p++) EPI_PAIR(accEp, p);
        }

        CP_WAIT0();
        __syncthreads();   // tile ct+2 staged; all warps past tile ct+1 MMAs
    }

    // row-sum: quad shuffle reduce, 4-wc merge
    #pragma unroll
    for (int s = 0; s < 4; s++) {
        rowsum[s] += __shfl_xor_sync(0xffffffffu, rowsum[s], 1);
        rowsum[s] += __shfl_xor_sync(0xffffffffu, rowsum[s], 2);
    }
    if (qt == 0) {
        #pragma unroll
        for (int s = 0; s < 4; s++)
            rsbuf[(wr * 32 + s * 8 + qid) * 4 + wc] = rowsum[s];
    }
    __syncthreads();

    // 128 threads: merge 16 candidate sets per row -> global 11 + rowsum
    if (tid < TM) {
        const int row = tid;
        const int rwr = row >> 5, rs = (row >> 3) & 3, rqid = row & 7;
        float hh[11];
        #pragma unroll
        for (int t = 0; t < KNN; t++) hh[t] = BIGF;
        #pragma unroll
        for (int cwc = 0; cwc < 4; cwc++)
            #pragma unroll
            for (int cqt = 0; cqt < 4; cqt++) {
                int owner = (rwr * 4 + cwc) * 32 + rqid * 4 + cqt;
                const float* d = heap + owner * 45 + rs * KNN;
                #pragma unroll
                for (int t = 0; t < KNN; t++) {
                    float v = d[t];
                    if (v < hh[10]) ins11(hh, v);
                }
            }
        int gr = rowbase + row;
        size_t base = (size_t)(h * NPTS + gr) * 12;
        #pragma unroll
        for (int t = 0; t < KNN; t++) g_ptopk[base + t] = hh[t];
        g_psum[h * NPTS + gr] = rsbuf[row * 4] + rsbuf[row * 4 + 1] +
                                rsbuf[row * 4 + 2] + rsbuf[row * 4 + 3];
    }
}

// ---- merge 2 halves per row + TSDM head ----
__global__ void tg_merge_kernel(const float* __restrict__ w_tsdm,
                                const float* __restrict__ b_tsdm)
{
    __shared__ float buf[128];
    int row = blockIdx.x * 128 + threadIdx.x;
    float hh[11];
    size_t b0 = (size_t)row * 12;
    size_t b1 = (size_t)(NPTS + row) * 12;
    #pragma unroll
    for (int t = 0; t < KNN; t++) hh[t] = g_ptopk[b0 + t];
    #pragma unroll
    for (int t = 0; t < KNN; t++) {
        float v = g_ptopk[b1 + t];
        if (v < hh[10]) ins11(hh, v);
    }
    float sep = (g_psum[row] + g_psum[NPTS + row]) * (1.f / (float)(NPTS - 1));
    float s11 = 0.f;
    #pragma unroll
    for (int t = 0; t < KNN; t++) s11 += hh[t];
    float comp = (s11 - hh[0]) * 0.1f;
    float disc = fabsf(comp * w_tsdm[0] + sep * w_tsdm[1] + b_tsdm[0]);
    buf[threadIdx.x] = disc;
    __syncthreads();
    if (threadIdx.x == 0) {
        float s = 0.f;
        for (int i = 0; i < 128; i++) s += buf[i];
        g_disc[blockIdx.x] = s;
    }
}

// ---- final: GDDM head + disc mean ----
__global__ void tg_final_kernel(const float* __restrict__ w_gddm,
                                const float* __restrict__ b_gddm,
                                float* __restrict__ out)
{
    __shared__ float buf[DIM];
    int d = threadIdx.x;
    float s = 0.f;
    for (int b = 0; b < 128; b++) s += g_colpart[b * DIM + d];
    buf[d] = (s * (1.f / (float)NPTS)) * w_gddm[d];
    __syncthreads();
    if (d == 0) {
        float t = 0.f;
        for (int i = 0; i < DIM; i++) t += buf[i];
        out[0] = fabsf(t + b_gddm[0]);
        float ds = 0.f;
        for (int i = 0; i < 64; i++) ds += g_disc[i];
        out[1] = ds * (1.f / (float)NPTS);
    }
}

extern "C" void kernel_launch(void* const* d_in, const int* in_sizes, int n_in,
                              void* d_out, int out_size) {
    const float* src    = (const float*)d_in[0];
    const float* tgt    = (const float*)d_in[1];
    const float* w_tsdm = (const float*)d_in[2];
    const float* b_tsdm = (const float*)d_in[3];
    const float* w_gddm = (const float*)d_in[4];
    const float* b_gddm = (const float*)d_in[5];
    float* out = (float*)d_out;

    cudaFuncSetAttribute(tg_main_kernel,
                         cudaFuncAttributeMaxDynamicSharedMemorySize, SM_TOTAL);

    tg_quant_kernel<<<NPTS / 8, 256>>>(tgt);
    tg_coldiff_kernel<<<128, DIM>>>(src, tgt);
    tg_main_kernel<<<128, NTHREADS, SM_TOTAL>>>();
    tg_merge_kernel<<<NPTS / 128, 128>>>(w_tsdm, b_tsdm);
    tg_final_kernel<<<1, DIM>>>(w_gddm, b_gddm, out);
}

// round 13
// speedup vs baseline: 2.5263x; 2.5263x over previous
#include <cuda_runtime.h>
#include <cstdint>

#define NPTS 8192
#define DIM  256           // elements per row (256 int8 bytes)
#define KNN  11
#define TM   128
#define TN   128
#define HALF 4096
#define NCT  32            // col tiles per CTA
#define NTHREADS 512
#define PAB  272           // smem pitch in BYTES (256 + 16)
#define BIGF 1e30f

// smem byte offsets
#define SMB_A   0
#define TILE_B  (128 * PAB)            // 34816 bytes per tile buffer
#define SMB_B   TILE_B                 // two B buffers follow A
#define SMB_RS  (TILE_B * 3)           // 104448
#define SM_TOTAL (SMB_RS + 2048)       // 106496 B

__device__ __align__(16) char g_xq[(size_t)NPTS * DIM];
__device__ float g_sq[NPTS];
__device__ float g_inv[NPTS];
__device__ __align__(16) float g_meta[2 * NPTS];   // (sq, inv) per column
__device__ float g_colpart[128 * DIM];
__device__ float g_psum[2 * NPTS];
__device__ float g_ptopk[(size_t)2 * NPTS * 12];
__device__ float g_disc[64];

__device__ __forceinline__ uint32_t smem_u32(const void* p) {
    uint32_t a;
    asm("{ .reg .u64 t; cvta.to.shared.u64 t, %1; cvt.u32.u64 %0, t; }"
        : "=r"(a) : "l"(p));
    return a;
}
__device__ __forceinline__ void cpasync16(uint32_t dst, const void* src) {
    asm volatile("cp.async.cg.shared.global [%0], [%1], 16;"
                 :: "r"(dst), "l"(src) : "memory");
}
#define CP_COMMIT() asm volatile("cp.async.commit_group;" ::: "memory")
#define CP_WAIT0()  asm volatile("cp.async.wait_group 0;" ::: "memory")

__device__ __forceinline__ void ldsm4(uint32_t& r0, uint32_t& r1,
                                      uint32_t& r2, uint32_t& r3, uint32_t a) {
    asm volatile("ldmatrix.sync.aligned.m8n8.x4.shared.b16 {%0,%1,%2,%3}, [%4];"
                 : "=r"(r0), "=r"(r1), "=r"(r2), "=r"(r3) : "r"(a));
}
__device__ __forceinline__ void mma_s8(int* d, const uint32_t* a,
                                       const uint32_t* b) {
    asm volatile(
        "mma.sync.aligned.m16n8k32.row.col.s32.s8.s8.s32 "
        "{%0,%1,%2,%3}, {%4,%5,%6,%7}, {%8,%9}, {%0,%1,%2,%3};"
        : "+r"(d[0]), "+r"(d[1]), "+r"(d[2]), "+r"(d[3])
        : "r"(a[0]), "r"(a[1]), "r"(a[2]), "r"(a[3]), "r"(b[0]), "r"(b[1]));
}

// insert d into ascending sorted 11-array (caller checked d < hh[10])
__device__ __forceinline__ void ins11(float* hh, float d) {
    hh[10] = d;
    #pragma unroll
    for (int t = 10; t > 0; t--) {
        float lo = fminf(hh[t - 1], hh[t]);
        float hi = fmaxf(hh[t - 1], hh[t]);
        hh[t - 1] = lo; hh[t] = hi;
    }
}

// ---- quantize rows to int8 + exact fp32 norms + per-row scale ----
__global__ void tg_quant_kernel(const float* __restrict__ x) {
    int row  = (blockIdx.x * blockDim.x + threadIdx.x) >> 5;
    int lane = threadIdx.x & 31;
    const float* r = x + (size_t)row * DIM + lane * 8;
    float4 v0 = *(const float4*)(r);
    float4 v1 = *(const float4*)(r + 4);
    float sq = v0.x * v0.x + v0.y * v0.y + v0.z * v0.z + v0.w * v0.w +
               v1.x * v1.x + v1.y * v1.y + v1.z * v1.z + v1.w * v1.w;
    float am = fmaxf(fmaxf(fmaxf(fabsf(v0.x), fabsf(v0.y)),
                           fmaxf(fabsf(v0.z), fabsf(v0.w))),
                     fmaxf(fmaxf(fabsf(v1.x), fabsf(v1.y)),
                           fmaxf(fabsf(v1.z), fabsf(v1.w))));
    #pragma unroll
    for (int o = 16; o; o >>= 1) {
        sq += __shfl_xor_sync(0xffffffffu, sq, o);
        am = fmaxf(am, __shfl_xor_sync(0xffffffffu, am, o));
    }
    float s = 127.f / am;
    int q[8];
    q[0] = __float2int_rn(v0.x * s); q[1] = __float2int_rn(v0.y * s);
    q[2] = __float2int_rn(v0.z * s); q[3] = __float2int_rn(v0.w * s);
    q[4] = __float2int_rn(v1.x * s); q[5] = __float2int_rn(v1.y * s);
    q[6] = __float2int_rn(v1.z * s); q[7] = __float2int_rn(v1.w * s);
    uint32_t p0 = (q[0] & 255) | ((q[1] & 255) << 8) |
                  ((q[2] & 255) << 16) | ((uint32_t)(q[3] & 255) << 24);
    uint32_t p1 = (q[4] & 255) | ((q[5] & 255) << 8) |
                  ((q[6] & 255) << 16) | ((uint32_t)(q[7] & 255) << 24);
    ((uint2*)(g_xq + (size_t)row * DIM))[lane] = make_uint2(p0, p1);
    if (lane == 0) {
        float inv = am * (1.f / 127.f);
        g_sq[row]  = sq;
        g_inv[row] = inv;
        g_meta[2 * row]     = sq;
        g_meta[2 * row + 1] = inv;
    }
}

// ---- GDDM column sums ----
__global__ void tg_coldiff_kernel(const float* __restrict__ src,
                                  const float* __restrict__ tgt) {
    int d = threadIdx.x;
    int b = blockIdx.x;
    int r0 = b * (NPTS / 128);
    float s = 0.f;
    for (int r = 0; r < NPTS / 128; r++) {
        size_t idx = (size_t)(r0 + r) * DIM + d;
        s += src[idx] - tgt[idx];
    }
    g_colpart[b * DIM + d] = s;
}

// ---- main: int8 IMMA Gram (ldmatrix) + scalar MUFU distance epilogue ----
__global__ void __launch_bounds__(NTHREADS, 1)
tg_main_kernel()
{
    extern __shared__ char sm[];
    const uint32_t smb = smem_u32(sm);
    float* rsbuf = (float*)(sm + SMB_RS);

    const int tid  = threadIdx.x;
    const int lane = tid & 31;
    const int warp = tid >> 5;
    const int wr   = warp >> 2;          // 0..3: 32-row group
    const int wc   = warp & 3;           // 0..3: 32-col group
    const int qid  = lane >> 2;          // 0..7
    const int qt   = lane & 3;           // 0..3
    const int rt   = blockIdx.x >> 1;
    const int h    = blockIdx.x & 1;
    const int rowbase = rt * TM;
    const int colhalf = h * HALF;

    // ldmatrix per-lane addresses
    const int lr8 = lane & 7;
    const int a_m  = ((lane >> 3) & 1) * 8 + lr8;
    const int a_kb = (lane >> 4) * 16;
    uint32_t aaddr[2];
    #pragma unroll
    for (int mi = 0; mi < 2; mi++)
        aaddr[mi] = smb + SMB_A +
                    (uint32_t)((wr * 32 + mi * 16 + a_m) * PAB) + a_kb;
    const int b_n  = ((lane >> 4) & 1) * 8 + lr8;
    const int b_kb = ((lane >> 3) & 1) * 16;
    uint32_t baddr0[2];
    #pragma unroll
    for (int g = 0; g < 2; g++)
        baddr0[g] = smb + SMB_B +
                    (uint32_t)((wc * 32 + g * 16 + b_n) * PAB) + b_kb;

    // stage A tile + B tile 0
    {
        const char* Ag = g_xq + (size_t)rowbase * DIM;
        const char* Bg = g_xq + (size_t)colhalf * DIM;
        #pragma unroll
        for (int p = 0; p < 4; p++) {
            int idx = tid + p * NTHREADS;    // 0..2047
            int r = idx >> 4, f = idx & 15;
            cpasync16(smb + SMB_A + r * PAB + f * 16, Ag + r * DIM + f * 16);
            cpasync16(smb + SMB_B + r * PAB + f * 16, Bg + r * DIM + f * 16);
        }
        CP_COMMIT();
    }

    float sa[4], pinv[4];
    #pragma unroll
    for (int s = 0; s < 4; s++) {
        int row = rowbase + wr * 32 + s * 8 + qid;
        sa[s]   = g_sq[row];
        pinv[s] = -2.f * g_inv[row];
    }

    float hreg[4][11];
    #pragma unroll
    for (int s = 0; s < 4; s++)
        #pragma unroll
        for (int t = 0; t < KNN; t++) hreg[s][t] = BIGF;
    float rowsum[4] = {0.f, 0.f, 0.f, 0.f};

    CP_WAIT0();
    __syncthreads();

    for (int ct = 0; ct < NCT; ct++) {
        // prefetch next B tile into the other buffer
        if (ct + 1 < NCT) {
            const char* Bg = g_xq + (size_t)(colhalf + (ct + 1) * TN) * DIM;
            uint32_t dst = smb + SMB_B + ((ct + 1) & 1) * TILE_B;
            #pragma unroll
            for (int p = 0; p < 4; p++) {
                int idx = tid + p * NTHREADS;
                int r = idx >> 4, f = idx & 15;
                cpasync16(dst + r * PAB + f * 16, Bg + r * DIM + f * 16);
            }
            CP_COMMIT();
        }

        const uint32_t bofs = (ct & 1) * TILE_B;

        int acc[2][4][4];
        #pragma unroll
        for (int mi = 0; mi < 2; mi++)
            #pragma unroll
            for (int ni = 0; ni < 4; ni++)
                #pragma unroll
                for (int j = 0; j < 4; j++) acc[mi][ni][j] = 0;

        #pragma unroll
        for (int kk = 0; kk < 8; kk++) {
            const uint32_t kby = kk * 32;       // 32 int8 = 32 B per k-step
            uint32_t af[2][4], bf[2][4];
            ldsm4(af[0][0], af[0][1], af[0][2], af[0][3], aaddr[0] + kby);
            ldsm4(af[1][0], af[1][1], af[1][2], af[1][3], aaddr[1] + kby);
            ldsm4(bf[0][0], bf[0][1], bf[0][2], bf[0][3], baddr0[0] + bofs + kby);
            ldsm4(bf[1][0], bf[1][1], bf[1][2], bf[1][3], baddr0[1] + bofs + kby);
            #pragma unroll
            for (int mi = 0; mi < 2; mi++)
                #pragma unroll
                for (int g = 0; g < 2; g++) {
                    mma_s8(acc[mi][2 * g + 0], af[mi], &bf[g][0]);
                    mma_s8(acc[mi][2 * g + 1], af[mi], &bf[g][2]);
                }
        }

        // epilogue: scalar dequant + distance; rsqrt on MUFU pipe
        const int colbase = colhalf + ct * TN;
        #pragma unroll
        for (int ni = 0; ni < 4; ni++) {
            const float4 mt = __ldg((const float4*)
                (g_meta + 2 * (colbase + wc * 32 + ni * 8 + 2 * qt)));
            #pragma unroll
            for (int mi = 0; mi < 2; mi++)
                #pragma unroll
                for (int hf = 0; hf < 2; hf++) {
                    const int s = mi * 2 + hf;
                    float f0 = __int2float_rn(acc[mi][ni][hf * 2 + 0]);
                    float f1 = __int2float_rn(acc[mi][ni][hf * 2 + 1]);
                    float d2a = fmaf(f0, mt.y * pinv[s], sa[s] + mt.x);
                    float d2b = fmaf(f1, mt.w * pinv[s], sa[s] + mt.z);
                    d2a = fmaxf(d2a, 1e-12f);
                    d2b = fmaxf(d2b, 1e-12f);
                    float da = d2a * rsqrtf(d2a);
                    float db = d2b * rsqrtf(d2b);
                    rowsum[s] += da + db;
                    if (da < hreg[s][10]) ins11(hreg[s], da);
                    if (db < hreg[s][10]) ins11(hreg[s], db);
                }
        }

        CP_WAIT0();
        __syncthreads();       // next B tile ready; all reads of cur buf done
    }

    // row-sum: quad shuffle reduce, 4-wc merge
    #pragma unroll
    for (int s = 0; s < 4; s++) {
        rowsum[s] += __shfl_xor_sync(0xffffffffu, rowsum[s], 1);
        rowsum[s] += __shfl_xor_sync(0xffffffffu, rowsum[s], 2);
    }
    if (qt == 0) {
        #pragma unroll
        for (int s = 0; s < 4; s++)
            rsbuf[(wr * 32 + s * 8 + qid) * 4 + wc] = rowsum[s];
    }

    // dump per-thread top-11 sets into smem (A region reused)
    float* dump = (float*)sm;            // [128 rows][16 sets][11]
    #pragma unroll
    for (int s = 0; s < 4; s++) {
        int row = wr * 32 + s * 8 + qid;
        int set = wc * 4 + qt;
        float* d = dump + (row * 16 + set) * 11;
        #pragma unroll
        for (int t = 0; t < KNN; t++) d[t] = hreg[s][t];
    }
    __syncthreads();

    // 128 threads: merge 16 sets per row -> global 11 + rowsum
    if (tid < TM) {
        const int row = tid;
        float hh[11];
        #pragma unroll
        for (int t = 0; t < KNN; t++) hh[t] = dump[(row * 16) * 11 + t];
        for (int set = 1; set < 16; set++) {
            const float* d = dump + (row * 16 + set) * 11;
            #pragma unroll
            for (int t = 0; t < KNN; t++) {
                float v = d[t];
                if (v < hh[10]) ins11(hh, v);
            }
        }
        int gr = rowbase + row;
        size_t base = (size_t)(h * NPTS + gr) * 12;
        #pragma unroll
        for (int t = 0; t < KNN; t++) g_ptopk[base + t] = hh[t];
        g_psum[h * NPTS + gr] = rsbuf[row * 4] + rsbuf[row * 4 + 1] +
                                rsbuf[row * 4 + 2] + rsbuf[row * 4 + 3];
    }
}

// ---- merge 2 halves per row + TSDM head ----
__global__ void tg_merge_kernel(const float* __restrict__ w_tsdm,
                                const float* __restrict__ b_tsdm)
{
    __shared__ float buf[128];
    int row = blockIdx.x * 128 + threadIdx.x;
    float hh[11];
    size_t b0 = (size_t)row * 12;
    size_t b1 = (size_t)(NPTS + row) * 12;
    #pragma unroll
    for (int t = 0; t < KNN; t++) hh[t] = g_ptopk[b0 + t];
    #pragma unroll
    for (int t = 0; t < KNN; t++) {
        float v = g_ptopk[b1 + t];
        if (v < hh[10]) ins11(hh, v);
    }
    float sep = (g_psum[row] + g_psum[NPTS + row]) * (1.f / (float)(NPTS - 1));
    float s11 = 0.f;
    #pragma unroll
    for (int t = 0; t < KNN; t++) s11 += hh[t];
    float comp = (s11 - hh[0]) * 0.1f;
    float disc = fabsf(comp * w_tsdm[0] + sep * w_tsdm[1] + b_tsdm[0]);
    buf[threadIdx.x] = disc;
    __syncthreads();
    if (threadIdx.x == 0) {
        float s = 0.f;
        for (int i = 0; i < 128; i++) s += buf[i];
        g_disc[blockIdx.x] = s;
    }
}

// ---- final: GDDM head + disc mean ----
__global__ void tg_final_kernel(const float* __restrict__ w_gddm,
                                const float* __restrict__ b_gddm,
                                float* __restrict__ out)
{
    __shared__ float buf[DIM];
    int d = threadIdx.x;
    float s = 0.f;
    for (int b = 0; b < 128; b++) s += g_colpart[b * DIM + d];
    buf[d] = (s * (1.f / (float)NPTS)) * w_gddm[d];
    __syncthreads();
    if (d == 0) {
        float t = 0.f;
        for (int i = 0; i < DIM; i++) t += buf[i];
        out[0] = fabsf(t + b_gddm[0]);
        float ds = 0.f;
        for (int i = 0; i < 64; i++) ds += g_disc[i];
        out[1] = ds * (1.f / (float)NPTS);
    }
}

extern "C" void kernel_launch(void* const* d_in, const int* in_sizes, int n_in,
                              void* d_out, int out_size) {
    const float* src    = (const float*)d_in[0];
    const float* tgt    = (const float*)d_in[1];
    const float* w_tsdm = (const float*)d_in[2];
    const float* b_tsdm = (const float*)d_in[3];
    const float* w_gddm = (const float*)d_in[4];
    const float* b_gddm = (const float*)d_in[5];
    float* out = (float*)d_out;

    cudaFuncSetAttribute(tg_main_kernel,
                         cudaFuncAttributeMaxDynamicSharedMemorySize, SM_TOTAL);

    tg_quant_kernel<<<NPTS / 8, 256>>>(tgt);
    tg_coldiff_kernel<<<128, DIM>>>(src, tgt);
    tg_main_kernel<<<128, NTHREADS, SM_TOTAL>>>();
    tg_merge_kernel<<<NPTS / 128, 128>>>(w_tsdm, b_tsdm);
    tg_final_kernel<<<1, DIM>>>(w_gddm, b_gddm, out);
}